// round 2
// baseline (speedup 1.0000x reference)
#include <cuda_runtime.h>
#include <cuda_bf16.h>
#include <math.h>

// Problem constants (fixed by the reference)
#define NN   50000
#define EE   400000
#define FIN  128
#define NH   3
#define DD   64
#define HD   192   // NH*DD
#define GG   64
#define PP   64

// ---------------- scratch (device globals; no allocation) ----------------
__device__ float g_fs[(size_t)NN * HD];
__device__ float g_fd[(size_t)NN * HD];
__device__ float g_h [(size_t)NN * HD];
__device__ float g_acc[(size_t)NN * HD];
__device__ float g_logits[(size_t)EE * NH];
__device__ float g_m  [(size_t)NN * NH];
__device__ float g_den[(size_t)NN * NH];
__device__ float g_hmean[(size_t)NN * DD];
__device__ float g_gsum[GG * DD];
__device__ float g_gcnt[GG];

// ---------------- helpers ----------------
__device__ __forceinline__ void atomicMaxF(float* addr, float val) {
    if (val >= 0.0f) atomicMax((int*)addr, __float_as_int(val));
    else             atomicMin((unsigned int*)addr, __float_as_uint(val));
}

static inline int cdiv(int a, int b) { return (a + b - 1) / b; }

// ---------------- init per layer ----------------
__global__ void k_init_layer() {
    int idx = blockIdx.x * blockDim.x + threadIdx.x;
    if (idx < NN * HD) g_acc[idx] = 0.0f;
    if (idx < NN * NH) { g_m[idx] = -INFINITY; g_den[idx] = 0.0f; }
    if (idx < GG * DD) g_gsum[idx] = 0.0f;
    if (idx < GG)      g_gcnt[idx] = 0.0f;
}

// ---------------- SGEMM: C[M,Nc] = A[M,K] @ B[K,Nc] ----------------
// BM=64, BN=64, BK=16, 256 threads, 4x4 micro-tile. K %16 == 0, Nc %64 == 0.
#define BM 64
#define BN 64
#define BK 16
__global__ void k_sgemm(const float* __restrict__ A, const float* __restrict__ B,
                        float* __restrict__ C, int M, int K, int Nc) {
    __shared__ float As[BK][BM];
    __shared__ float Bs[BK][BN];
    int tid  = threadIdx.x;
    int row0 = blockIdx.y * BM;
    int col0 = blockIdx.x * BN;
    int arow = tid >> 2;          // 0..63
    int acol = (tid & 3) * 4;     // 0,4,8,12
    int brow = tid >> 4;          // 0..15
    int bcol = (tid & 15) * 4;    // 0..60
    int ty = tid >> 4, tx = tid & 15;
    float acc[4][4] = {};

    for (int k0 = 0; k0 < K; k0 += BK) {
        float4 av = make_float4(0.f, 0.f, 0.f, 0.f);
        int ar = row0 + arow;
        if (ar < M) av = *(const float4*)(A + (size_t)ar * K + k0 + acol);
        As[acol + 0][arow] = av.x;
        As[acol + 1][arow] = av.y;
        As[acol + 2][arow] = av.z;
        As[acol + 3][arow] = av.w;
        float4 bv = *(const float4*)(B + (size_t)(k0 + brow) * Nc + col0 + bcol);
        *(float4*)&Bs[brow][bcol] = bv;
        __syncthreads();
#pragma unroll
        for (int kk = 0; kk < BK; kk++) {
            float ra[4], rb[4];
#pragma unroll
            for (int i = 0; i < 4; i++) ra[i] = As[kk][ty * 4 + i];
#pragma unroll
            for (int j = 0; j < 4; j++) rb[j] = Bs[kk][tx * 4 + j];
#pragma unroll
            for (int i = 0; i < 4; i++)
#pragma unroll
                for (int j = 0; j < 4; j++) acc[i][j] = fmaf(ra[i], rb[j], acc[i][j]);
        }
        __syncthreads();
    }
#pragma unroll
    for (int i = 0; i < 4; i++) {
        int r = row0 + ty * 4 + i;
        if (r < M) {
            float4 v = make_float4(acc[i][0], acc[i][1], acc[i][2], acc[i][3]);
            *(float4*)(C + (size_t)r * Nc + col0 + tx * 4) = v;
        }
    }
}

// ---------------- edge kernels ----------------
// logits[e,h] = a[h] . leaky_relu(fs[src]+fd[dst], 0.2); atomic segment max on dst
__global__ void k_edge_logits(const int* __restrict__ src, const int* __restrict__ dst,
                              const float* __restrict__ attn) {
    int idx = blockIdx.x * blockDim.x + threadIdx.x;
    if (idx >= EE * NH) return;
    int e = idx / NH, h = idx % NH;
    int s = src[e], t = dst[e];
    const float4* pf = (const float4*)(g_fs + (size_t)s * HD + h * DD);
    const float4* pd = (const float4*)(g_fd + (size_t)t * HD + h * DD);
    const float4* pa = (const float4*)(attn + h * DD);
    float acc = 0.0f;
#pragma unroll
    for (int i = 0; i < 16; i++) {
        float4 a4 = __ldg(pa + i);
        float4 f  = pf[i];
        float4 d  = pd[i];
        float v;
        v = f.x + d.x; v = v > 0.f ? v : 0.2f * v; acc = fmaf(a4.x, v, acc);
        v = f.y + d.y; v = v > 0.f ? v : 0.2f * v; acc = fmaf(a4.y, v, acc);
        v = f.z + d.z; v = v > 0.f ? v : 0.2f * v; acc = fmaf(a4.z, v, acc);
        v = f.w + d.w; v = v > 0.f ? v : 0.2f * v; acc = fmaf(a4.w, v, acc);
    }
    g_logits[idx] = acc;
    atomicMaxF(&g_m[t * NH + h], acc);
}

__global__ void k_finalize_m() {
    int idx = blockIdx.x * blockDim.x + threadIdx.x;
    if (idx >= NN * NH) return;
    float v = g_m[idx];
    if (!isfinite(v)) v = 0.0f;
    g_m[idx] = v;
}

__global__ void k_edge_exp(const int* __restrict__ dst) {
    int idx = blockIdx.x * blockDim.x + threadIdx.x;
    if (idx >= EE * NH) return;
    int e = idx / NH, h = idx % NH;
    int t = dst[e];
    float ex = expf(g_logits[idx] - g_m[t * NH + h]);
    g_logits[idx] = ex;
    atomicAdd(&g_den[t * NH + h], ex);
}

__global__ void k_edge_agg(const int* __restrict__ src, const int* __restrict__ dst) {
    int idx = blockIdx.x * blockDim.x + threadIdx.x;
    if (idx >= EE * NH) return;
    int e = idx / NH, h = idx % NH;
    int s = src[e], t = dst[e];
    float alpha = g_logits[idx] / fmaxf(g_den[t * NH + h], 1e-9f);
    const float4* pf = (const float4*)(g_fs + (size_t)s * HD + h * DD);
    float* po = g_acc + (size_t)t * HD + h * DD;
#pragma unroll
    for (int i = 0; i < 16; i++) {
        float4 f = pf[i];
        atomicAdd(po + i * 4 + 0, alpha * f.x);
        atomicAdd(po + i * 4 + 1, alpha * f.y);
        atomicAdd(po + i * 4 + 2, alpha * f.z);
        atomicAdd(po + i * 4 + 3, alpha * f.w);
    }
}

// h = acc + bias  (layers 1,2)
__global__ void k_bias_out(const float* __restrict__ bias) {
    int idx = blockIdx.x * blockDim.x + threadIdx.x;
    if (idx >= NN * HD) return;
    g_h[idx] = g_acc[idx] + __ldg(bias + idx % HD);
}

// hmean = mean over heads of (acc + bias)  (layer 3)
__global__ void k_mean_out(const float* __restrict__ bias) {
    int idx = blockIdx.x * blockDim.x + threadIdx.x;
    if (idx >= NN * DD) return;
    int n = idx / DD, d = idx % DD;
    const float* p = g_acc + (size_t)n * HD;
    float v = (p[d] + __ldg(bias + d))
            + (p[DD + d] + __ldg(bias + DD + d))
            + (p[2 * DD + d] + __ldg(bias + 2 * DD + d));
    g_hmean[idx] = v * (1.0f / 3.0f);
}

// per-graph mean pooling (accumulate)
__global__ void k_pool(const int* __restrict__ gid) {
    int idx = blockIdx.x * blockDim.x + threadIdx.x;
    if (idx >= NN * DD) return;
    int n = idx / DD, d = idx % DD;
    int g = gid[n];
    atomicAdd(&g_gsum[g * DD + d], g_hmean[idx]);
    if (d == 0) atomicAdd(&g_gcnt[g], 1.0f);
}

// ---------------- pattern branch + classifier head ----------------
// one block per graph, 128 threads
__global__ void k_head(const float* __restrict__ p1, const float* __restrict__ p2,
                       const float* __restrict__ p3,
                       const float* __restrict__ Wex, const float* __restrict__ bex,
                       const float* __restrict__ Wpat, const float* __restrict__ bpat,
                       const float* __restrict__ Wc1, const float* __restrict__ bc1,
                       const float* __restrict__ Wc2, const float* __restrict__ bc2,
                       const float* __restrict__ Wc3, const float* __restrict__ bc3,
                       float* __restrict__ out) {
    int g = blockIdx.x;
    int tid = threadIdx.x;
    __shared__ float s_ex[96];
    __shared__ float s_x[128];
    __shared__ float s_c1[64];
    __shared__ float s_c2[32];

    // ex = [p1@Wex+bex, p2@Wex+bex, p3@Wex+bex]
    if (tid < 96) {
        int part = tid / 32, j = tid % 32;
        const float* p = (part == 0) ? p1 : (part == 1) ? p2 : p3;
        float acc = bex[j];
        for (int k = 0; k < PP; k++) acc = fmaf(p[g * PP + k], Wex[k * 32 + j], acc);
        s_ex[tid] = acc;
    }
    __syncthreads();

    if (tid < 64) {
        // gnn_out = gsum / max(cnt,1)
        float cnt = fmaxf(g_gcnt[g], 1.0f);
        s_x[tid] = g_gsum[g * DD + tid] / cnt;
    } else {
        int j = tid - 64;   // px column
        float acc = bpat[j];
        for (int k = 0; k < 96; k++) acc = fmaf(s_ex[k], Wpat[k * PP + j], acc);
        s_x[tid] = acc > 0.f ? acc : 0.01f * acc;
    }
    __syncthreads();

    if (tid < 64) {
        float acc = bc1[tid];
        for (int k = 0; k < 128; k++) acc = fmaf(s_x[k], Wc1[k * 64 + tid], acc);
        s_c1[tid] = acc > 0.f ? acc : 0.01f * acc;
    }
    __syncthreads();

    if (tid < 32) {
        float acc = bc2[tid];
        for (int k = 0; k < 64; k++) acc = fmaf(s_c1[k], Wc2[k * 32 + tid], acc);
        s_c2[tid] = acc > 0.f ? acc : 0.01f * acc;
    }
    __syncthreads();

    if (tid < 2) {
        float acc = bc3[tid];
        for (int k = 0; k < 32; k++) acc = fmaf(s_c2[k], Wc3[k * 2 + tid], acc);
        out[g * 2 + tid] = acc;
    }
}

// ---------------- driver ----------------
static void run_layer(const float* x, int K,
                      const float* Ws, const float* Wd, const float* attn,
                      const float* bias, const int* src, const int* dst,
                      float* p_fs, float* p_fd, bool last) {
    const int T = 256;
    k_init_layer<<<cdiv(NN * HD, T), T>>>();
    dim3 grid(HD / BN, cdiv(NN, BM));
    k_sgemm<<<grid, 256>>>(x, Ws, p_fs, NN, K, HD);
    k_sgemm<<<grid, 256>>>(x, Wd, p_fd, NN, K, HD);
    k_edge_logits<<<cdiv(EE * NH, T), T>>>(src, dst, attn);
    k_finalize_m<<<cdiv(NN * NH, T), T>>>();
    k_edge_exp<<<cdiv(EE * NH, T), T>>>(dst);
    k_edge_agg<<<cdiv(EE * NH, T), T>>>(src, dst);
    if (!last) k_bias_out<<<cdiv(NN * HD, T), T>>>(bias);
    else       k_mean_out<<<cdiv(NN * DD, T), T>>>(bias);
}

extern "C" void kernel_launch(void* const* d_in, const int* in_sizes, int n_in,
                              void* d_out, int out_size) {
    const float* inputs = (const float*)d_in[0];
    const int*   src    = (const int*)d_in[1];
    const int*   dst    = (const int*)d_in[2];
    const int*   gid    = (const int*)d_in[3];
    const float* p1     = (const float*)d_in[4];
    const float* p2     = (const float*)d_in[5];
    const float* p3     = (const float*)d_in[6];
    const float* W1s = (const float*)d_in[7],  *W1d = (const float*)d_in[8];
    const float* a1  = (const float*)d_in[9],  *b1  = (const float*)d_in[10];
    const float* W2s = (const float*)d_in[11], *W2d = (const float*)d_in[12];
    const float* a2  = (const float*)d_in[13], *b2  = (const float*)d_in[14];
    const float* W3s = (const float*)d_in[15], *W3d = (const float*)d_in[16];
    const float* a3  = (const float*)d_in[17], *b3  = (const float*)d_in[18];
    const float* Wex = (const float*)d_in[19], *bex = (const float*)d_in[20];
    const float* Wpat= (const float*)d_in[21], *bpat= (const float*)d_in[22];
    const float* Wc1 = (const float*)d_in[23], *bc1 = (const float*)d_in[24];
    const float* Wc2 = (const float*)d_in[25], *bc2 = (const float*)d_in[26];
    const float* Wc3 = (const float*)d_in[27], *bc3 = (const float*)d_in[28];

    float *p_fs, *p_fd, *p_h;
    cudaGetSymbolAddress((void**)&p_fs, g_fs);
    cudaGetSymbolAddress((void**)&p_fd, g_fd);
    cudaGetSymbolAddress((void**)&p_h,  g_h);

    run_layer(inputs, FIN, W1s, W1d, a1, b1, src, dst, p_fs, p_fd, false);
    run_layer(p_h,    HD,  W2s, W2d, a2, b2, src, dst, p_fs, p_fd, false);
    run_layer(p_h,    HD,  W3s, W3d, a3, b3, src, dst, p_fs, p_fd, true);

    const int T = 256;
    k_pool<<<cdiv(NN * DD, T), T>>>(gid);
    k_head<<<GG, 128>>>(p1, p2, p3, Wex, bex, Wpat, bpat,
                        Wc1, bc1, Wc2, bc2, Wc3, bc3, (float*)d_out);
}

// round 3
// speedup vs baseline: 2.3506x; 2.3506x over previous
#include <cuda_runtime.h>
#include <cuda_bf16.h>
#include <math.h>

// Problem constants (fixed by the reference)
#define NN   50000
#define EE   400000
#define FIN  128
#define NH   3
#define DD   64
#define HD   192   // NH*DD
#define GG   64
#define PP   64

// ---------------- scratch (device globals; no allocation) ----------------
__device__ float g_fs[(size_t)NN * HD];
__device__ float g_fd[(size_t)NN * HD];
__device__ float g_h [(size_t)NN * HD];
__device__ float g_acc[(size_t)NN * HD];   // layer-3 per-head outputs
__device__ float g_gsum[GG * DD];
__device__ float g_gcnt[GG];
// CSR by dst (built once per launch; dst does not change across layers)
__device__ int g_deg[NN];
__device__ int g_off[NN + 1];
__device__ int g_cur[NN];
__device__ int g_esrc[EE];

static inline int cdiv(int a, int b) { return (a + b - 1) / b; }

// ---------------- launch-wide init ----------------
__global__ void k_init() {
    int idx = blockIdx.x * blockDim.x + threadIdx.x;
    if (idx < NN) g_deg[idx] = 0;
    if (idx < GG * DD) g_gsum[idx] = 0.0f;
    if (idx < GG) g_gcnt[idx] = 0.0f;
}

__global__ void k_hist(const int* __restrict__ dst) {
    int e = blockIdx.x * blockDim.x + threadIdx.x;
    if (e < EE) atomicAdd(&g_deg[dst[e]], 1);
}

// single-block exclusive scan of g_deg -> g_off (and g_cur copy)
__global__ void k_scan() {
    __shared__ int s_warp[32];
    int tid = threadIdx.x;
    int lane = tid & 31, wid = tid >> 5;
    int running = 0;
    for (int base = 0; base < NN; base += 1024) {
        int i = base + tid;
        int v = (i < NN) ? g_deg[i] : 0;
        int x = v;
#pragma unroll
        for (int o = 1; o < 32; o <<= 1) {
            int y = __shfl_up_sync(0xFFFFFFFFu, x, o);
            if (lane >= o) x += y;
        }
        if (lane == 31) s_warp[wid] = x;
        __syncthreads();
        if (wid == 0) {
            int w = s_warp[lane];
#pragma unroll
            for (int o = 1; o < 32; o <<= 1) {
                int y = __shfl_up_sync(0xFFFFFFFFu, w, o);
                if (lane >= o) w += y;
            }
            s_warp[lane] = w;
        }
        __syncthreads();
        int excl = running + x - v + (wid > 0 ? s_warp[wid - 1] : 0);
        if (i < NN) { g_off[i] = excl; g_cur[i] = excl; }
        int total = s_warp[31];
        __syncthreads();
        running += total;
    }
    if (tid == 0) g_off[NN] = running;
}

__global__ void k_scatter(const int* __restrict__ src, const int* __restrict__ dst) {
    int e = blockIdx.x * blockDim.x + threadIdx.x;
    if (e >= EE) return;
    int t = dst[e];
    int pos = atomicAdd(&g_cur[t], 1);
    g_esrc[pos] = src[e];
}

// ---------------- SGEMM: C[M,Nc] = A[M,K] @ B[K,Nc] ----------------
#define BM 64
#define BN 64
#define BK 16
__global__ void k_sgemm(const float* __restrict__ A, const float* __restrict__ B,
                        float* __restrict__ C, int M, int K, int Nc) {
    __shared__ float As[BK][BM];
    __shared__ float Bs[BK][BN];
    int tid  = threadIdx.x;
    int row0 = blockIdx.y * BM;
    int col0 = blockIdx.x * BN;
    int arow = tid >> 2;
    int acol = (tid & 3) * 4;
    int brow = tid >> 4;
    int bcol = (tid & 15) * 4;
    int ty = tid >> 4, tx = tid & 15;
    float acc[4][4] = {};

    for (int k0 = 0; k0 < K; k0 += BK) {
        float4 av = make_float4(0.f, 0.f, 0.f, 0.f);
        int ar = row0 + arow;
        if (ar < M) av = *(const float4*)(A + (size_t)ar * K + k0 + acol);
        As[acol + 0][arow] = av.x;
        As[acol + 1][arow] = av.y;
        As[acol + 2][arow] = av.z;
        As[acol + 3][arow] = av.w;
        float4 bv = *(const float4*)(B + (size_t)(k0 + brow) * Nc + col0 + bcol);
        *(float4*)&Bs[brow][bcol] = bv;
        __syncthreads();
#pragma unroll
        for (int kk = 0; kk < BK; kk++) {
            float ra[4], rb[4];
#pragma unroll
            for (int i = 0; i < 4; i++) ra[i] = As[kk][ty * 4 + i];
#pragma unroll
            for (int j = 0; j < 4; j++) rb[j] = Bs[kk][tx * 4 + j];
#pragma unroll
            for (int i = 0; i < 4; i++)
#pragma unroll
                for (int j = 0; j < 4; j++) acc[i][j] = fmaf(ra[i], rb[j], acc[i][j]);
        }
        __syncthreads();
    }
#pragma unroll
    for (int i = 0; i < 4; i++) {
        int r = row0 + ty * 4 + i;
        if (r < M) {
            float4 v = make_float4(acc[i][0], acc[i][1], acc[i][2], acc[i][3]);
            *(float4*)(C + (size_t)r * Nc + col0 + tx * 4) = v;
        }
    }
}

// ---------------- fused GATv2 edge softmax + aggregation ----------------
// One warp per (dst node, head). Online softmax over in-edges (CSR order).
// out[n, h*64+d] = sum_e alpha * fs[src_e] + bias   (single fs gather per edge)
__global__ void k_gat(const float* __restrict__ attn, const float* __restrict__ bias,
                      float* __restrict__ out) {
    int w = (blockIdx.x * blockDim.x + threadIdx.x) >> 5;
    int lane = threadIdx.x & 31;
    if (w >= NN * NH) return;
    int n = w / NH, h = w - n * NH;
    int base = h * DD + lane * 2;

    float2 fd2 = *(const float2*)(g_fd + (size_t)n * HD + base);
    float2 a2  = __ldg((const float2*)(attn + base));

    float m = -INFINITY, den = 0.f, accx = 0.f, accy = 0.f;
    int beg = g_off[n], end = g_off[n + 1];
    for (int i = beg; i < end; i++) {
        int s = g_esrc[i];
        float2 fs2 = *(const float2*)(g_fs + (size_t)s * HD + base);
        float vx = fs2.x + fd2.x; vx = vx > 0.f ? vx : 0.2f * vx;
        float vy = fs2.y + fd2.y; vy = vy > 0.f ? vy : 0.2f * vy;
        float p = fmaf(a2.x, vx, a2.y * vy);
#pragma unroll
        for (int o = 16; o; o >>= 1) p += __shfl_xor_sync(0xFFFFFFFFu, p, o);
        if (p <= m) {
            float ex = expf(p - m);
            den += ex;
            accx = fmaf(ex, fs2.x, accx);
            accy = fmaf(ex, fs2.y, accy);
        } else {
            float sc = expf(m - p);   // exp(-inf)=0 handles first edge
            den = fmaf(den, sc, 1.f);
            accx = fmaf(accx, sc, fs2.x);
            accy = fmaf(accy, sc, fs2.y);
            m = p;
        }
    }
    float inv = 1.f / fmaxf(den, 1e-9f);
    float2 b2 = __ldg((const float2*)(bias + base));
    float2 o2;
    o2.x = fmaf(accx, inv, b2.x);
    o2.y = fmaf(accy, inv, b2.y);
    *(float2*)(out + (size_t)n * HD + base) = o2;
}

// layer-3: mean over heads (bias already included per head) + graph pooling
__global__ void k_poolmean(const int* __restrict__ gid) {
    int idx = blockIdx.x * blockDim.x + threadIdx.x;
    if (idx >= NN * DD) return;
    int n = idx / DD, d = idx - n * DD;
    const float* p = g_acc + (size_t)n * HD;
    float v = (p[d] + p[DD + d] + p[2 * DD + d]) * (1.0f / 3.0f);
    int g = gid[n];
    atomicAdd(&g_gsum[g * DD + d], v);
    if (d == 0) atomicAdd(&g_gcnt[g], 1.0f);
}

// ---------------- pattern branch + classifier head ----------------
__global__ void k_head(const float* __restrict__ p1, const float* __restrict__ p2,
                       const float* __restrict__ p3,
                       const float* __restrict__ Wex, const float* __restrict__ bex,
                       const float* __restrict__ Wpat, const float* __restrict__ bpat,
                       const float* __restrict__ Wc1, const float* __restrict__ bc1,
                       const float* __restrict__ Wc2, const float* __restrict__ bc2,
                       const float* __restrict__ Wc3, const float* __restrict__ bc3,
                       float* __restrict__ out) {
    int g = blockIdx.x;
    int tid = threadIdx.x;
    __shared__ float s_ex[96];
    __shared__ float s_x[128];
    __shared__ float s_c1[64];
    __shared__ float s_c2[32];

    if (tid < 96) {
        int part = tid / 32, j = tid % 32;
        const float* p = (part == 0) ? p1 : (part == 1) ? p2 : p3;
        float acc = bex[j];
        for (int k = 0; k < PP; k++) acc = fmaf(p[g * PP + k], Wex[k * 32 + j], acc);
        s_ex[tid] = acc;
    }
    __syncthreads();

    if (tid < 64) {
        float cnt = fmaxf(g_gcnt[g], 1.0f);
        s_x[tid] = g_gsum[g * DD + tid] / cnt;
    } else {
        int j = tid - 64;
        float acc = bpat[j];
        for (int k = 0; k < 96; k++) acc = fmaf(s_ex[k], Wpat[k * PP + j], acc);
        s_x[tid] = acc > 0.f ? acc : 0.01f * acc;
    }
    __syncthreads();

    if (tid < 64) {
        float acc = bc1[tid];
        for (int k = 0; k < 128; k++) acc = fmaf(s_x[k], Wc1[k * 64 + tid], acc);
        s_c1[tid] = acc > 0.f ? acc : 0.01f * acc;
    }
    __syncthreads();

    if (tid < 32) {
        float acc = bc2[tid];
        for (int k = 0; k < 64; k++) acc = fmaf(s_c1[k], Wc2[k * 32 + tid], acc);
        s_c2[tid] = acc > 0.f ? acc : 0.01f * acc;
    }
    __syncthreads();

    if (tid < 2) {
        float acc = bc3[tid];
        for (int k = 0; k < 32; k++) acc = fmaf(s_c2[k], Wc3[k * 2 + tid], acc);
        out[g * 2 + tid] = acc;
    }
}

// ---------------- driver ----------------
static void run_layer(const float* x, int K,
                      const float* Ws, const float* Wd, const float* attn,
                      const float* bias, float* p_fs, float* p_fd, float* out) {
    dim3 grid(HD / BN, cdiv(NN, BM));
    k_sgemm<<<grid, 256>>>(x, Ws, p_fs, NN, K, HD);
    k_sgemm<<<grid, 256>>>(x, Wd, p_fd, NN, K, HD);
    k_gat<<<cdiv(NN * NH * 32, 256), 256>>>(attn, bias, out);
}

extern "C" void kernel_launch(void* const* d_in, const int* in_sizes, int n_in,
                              void* d_out, int out_size) {
    const float* inputs = (const float*)d_in[0];
    const int*   src    = (const int*)d_in[1];
    const int*   dst    = (const int*)d_in[2];
    const int*   gid    = (const int*)d_in[3];
    const float* p1     = (const float*)d_in[4];
    const float* p2     = (const float*)d_in[5];
    const float* p3     = (const float*)d_in[6];
    const float* W1s = (const float*)d_in[7],  *W1d = (const float*)d_in[8];
    const float* a1  = (const float*)d_in[9],  *b1  = (const float*)d_in[10];
    const float* W2s = (const float*)d_in[11], *W2d = (const float*)d_in[12];
    const float* a2  = (const float*)d_in[13], *b2  = (const float*)d_in[14];
    const float* W3s = (const float*)d_in[15], *W3d = (const float*)d_in[16];
    const float* a3  = (const float*)d_in[17], *b3  = (const float*)d_in[18];
    const float* Wex = (const float*)d_in[19], *bex = (const float*)d_in[20];
    const float* Wpat= (const float*)d_in[21], *bpat= (const float*)d_in[22];
    const float* Wc1 = (const float*)d_in[23], *bc1 = (const float*)d_in[24];
    const float* Wc2 = (const float*)d_in[25], *bc2 = (const float*)d_in[26];
    const float* Wc3 = (const float*)d_in[27], *bc3 = (const float*)d_in[28];

    float *p_fs, *p_fd, *p_h, *p_acc;
    cudaGetSymbolAddress((void**)&p_fs,  g_fs);
    cudaGetSymbolAddress((void**)&p_fd,  g_fd);
    cudaGetSymbolAddress((void**)&p_h,   g_h);
    cudaGetSymbolAddress((void**)&p_acc, g_acc);

    const int T = 256;
    // CSR build (dst is the same for all layers)
    k_init<<<cdiv(NN, T), T>>>();
    k_hist<<<cdiv(EE, T), T>>>(dst);
    k_scan<<<1, 1024>>>();
    k_scatter<<<cdiv(EE, T), T>>>(src, dst);

    run_layer(inputs, FIN, W1s, W1d, a1, b1, p_fs, p_fd, p_h);
    run_layer(p_h,    HD,  W2s, W2d, a2, b2, p_fs, p_fd, p_h);
    run_layer(p_h,    HD,  W3s, W3d, a3, b3, p_fs, p_fd, p_acc);

    k_poolmean<<<cdiv(NN * DD, T), T>>>(gid);
    k_head<<<GG, 128>>>(p1, p2, p3, Wex, bex, Wpat, bpat,
                        Wc1, bc1, Wc2, bc2, Wc3, bc3, (float*)d_out);
}

// round 4
// speedup vs baseline: 3.4373x; 1.4623x over previous
#include <cuda_runtime.h>
#include <cuda_bf16.h>
#include <math.h>
#include <stdint.h>

// Problem constants (fixed by the reference)
#define NN   50000
#define EE   400000
#define FIN  128
#define NH   3
#define DD   64
#define HD   192   // NH*DD
#define GG   64
#define PP   64

// ---------------- scratch (device globals; no allocation) ----------------
__device__ float g_fs[(size_t)NN * HD];
__device__ float g_fd[(size_t)NN * HD];
__device__ float g_h [(size_t)NN * HD];
__device__ float g_acc[(size_t)NN * HD];   // layer-3 per-head outputs
__device__ float g_gsum[GG * DD];
__device__ float g_gcnt[GG];
// CSR by dst (built once per launch; dst does not change across layers)
__device__ int g_deg[NN];
__device__ int g_off[NN + 1];
__device__ int g_cur[NN];
__device__ int g_esrc[EE];

static inline int cdiv(int a, int b) { return (a + b - 1) / b; }

__device__ __forceinline__ float to_tf32(float x) {
    uint32_t u; asm("cvt.rna.tf32.f32 %0, %1;" : "=r"(u) : "f"(x));
    return __uint_as_float(u);
}

// ---------------- launch-wide init ----------------
__global__ void k_init() {
    int idx = blockIdx.x * blockDim.x + threadIdx.x;
    if (idx < NN) g_deg[idx] = 0;
    if (idx < GG * DD) g_gsum[idx] = 0.0f;
    if (idx < GG) g_gcnt[idx] = 0.0f;
}

__global__ void k_hist(const int* __restrict__ dst) {
    int e = blockIdx.x * blockDim.x + threadIdx.x;
    if (e < EE) atomicAdd(&g_deg[dst[e]], 1);
}

// single-block exclusive scan of g_deg -> g_off (and g_cur copy)
__global__ void k_scan() {
    __shared__ int s_warp[32];
    int tid = threadIdx.x;
    int lane = tid & 31, wid = tid >> 5;
    int running = 0;
    for (int base = 0; base < NN; base += 1024) {
        int i = base + tid;
        int v = (i < NN) ? g_deg[i] : 0;
        int x = v;
#pragma unroll
        for (int o = 1; o < 32; o <<= 1) {
            int y = __shfl_up_sync(0xFFFFFFFFu, x, o);
            if (lane >= o) x += y;
        }
        if (lane == 31) s_warp[wid] = x;
        __syncthreads();
        if (wid == 0) {
            int w = s_warp[lane];
#pragma unroll
            for (int o = 1; o < 32; o <<= 1) {
                int y = __shfl_up_sync(0xFFFFFFFFu, w, o);
                if (lane >= o) w += y;
            }
            s_warp[lane] = w;
        }
        __syncthreads();
        int excl = running + x - v + (wid > 0 ? s_warp[wid - 1] : 0);
        if (i < NN) { g_off[i] = excl; g_cur[i] = excl; }
        int total = s_warp[31];
        __syncthreads();
        running += total;
    }
    if (tid == 0) g_off[NN] = running;
}

__global__ void k_scatter(const int* __restrict__ src, const int* __restrict__ dst) {
    int e = blockIdx.x * blockDim.x + threadIdx.x;
    if (e >= EE) return;
    int t = dst[e];
    int pos = atomicAdd(&g_cur[t], 1);
    g_esrc[pos] = src[e];
}

// ---------------- tf32 tensor-core GEMM: C[M,Nc] = A[M,K] @ B[K,Nc] ----------------
// BM=128, BN=64, BK=32, 256 threads (8 warps: 4x2), 32x32 per warp via m16n8k8.
// Requires K % 32 == 0, Nc % 64 == 0.
#define TBM 128
#define TBN 64
#define TBK 32
#define APAD 4
#define BPAD 4
__global__ void k_gemm_tf32(const float* __restrict__ A, const float* __restrict__ B,
                            float* __restrict__ C, int M, int K, int Nc) {
    __shared__ float As[TBK][TBM + APAD];   // [k][m]
    __shared__ float Bs[TBK][TBN + BPAD];   // [k][n]
    int tid = threadIdx.x;
    int warp = tid >> 5, lane = tid & 31;
    int warp_m = warp & 3, warp_n = warp >> 2;     // 4 x 2 warp grid
    int row0 = blockIdx.y * TBM;
    int col0 = blockIdx.x * TBN;
    int gid = lane >> 2, tig = lane & 3;           // groupID, thread-in-group

    float c[2][4][4] = {};

    for (int k0 = 0; k0 < K; k0 += TBK) {
        // load A tile (128x32), transpose into As[k][m], cvt tf32
#pragma unroll
        for (int i = 0; i < 4; i++) {
            int idx = tid + i * 256;
            int r = idx >> 3, c4 = (idx & 7) * 4;
            int ar = row0 + r;
            float4 v = make_float4(0.f, 0.f, 0.f, 0.f);
            if (ar < M) v = *(const float4*)(A + (size_t)ar * K + k0 + c4);
            As[c4 + 0][r] = to_tf32(v.x);
            As[c4 + 1][r] = to_tf32(v.y);
            As[c4 + 2][r] = to_tf32(v.z);
            As[c4 + 3][r] = to_tf32(v.w);
        }
        // load B tile (32x64) into Bs[k][n], cvt tf32
#pragma unroll
        for (int i = 0; i < 2; i++) {
            int idx = tid + i * 256;
            int r = idx >> 4, c4 = (idx & 15) * 4;
            float4 v = *(const float4*)(B + (size_t)(k0 + r) * Nc + col0 + c4);
            Bs[r][c4 + 0] = to_tf32(v.x);
            Bs[r][c4 + 1] = to_tf32(v.y);
            Bs[r][c4 + 2] = to_tf32(v.z);
            Bs[r][c4 + 3] = to_tf32(v.w);
        }
        __syncthreads();

#pragma unroll
        for (int ks = 0; ks < TBK / 8; ks++) {
            int kb = ks * 8;
            uint32_t a[2][4], b[4][2];
#pragma unroll
            for (int mt = 0; mt < 2; mt++) {
                int r = warp_m * 32 + mt * 16 + gid;
                a[mt][0] = __float_as_uint(As[kb + tig][r]);
                a[mt][1] = __float_as_uint(As[kb + tig][r + 8]);
                a[mt][2] = __float_as_uint(As[kb + tig + 4][r]);
                a[mt][3] = __float_as_uint(As[kb + tig + 4][r + 8]);
            }
#pragma unroll
            for (int nt = 0; nt < 4; nt++) {
                int cn = warp_n * 32 + nt * 8 + gid;
                b[nt][0] = __float_as_uint(Bs[kb + tig][cn]);
                b[nt][1] = __float_as_uint(Bs[kb + tig + 4][cn]);
            }
#pragma unroll
            for (int mt = 0; mt < 2; mt++)
#pragma unroll
                for (int nt = 0; nt < 4; nt++)
                    asm volatile(
                        "mma.sync.aligned.m16n8k8.row.col.f32.tf32.tf32.f32 "
                        "{%0,%1,%2,%3}, {%4,%5,%6,%7}, {%8,%9}, {%0,%1,%2,%3};"
                        : "+f"(c[mt][nt][0]), "+f"(c[mt][nt][1]),
                          "+f"(c[mt][nt][2]), "+f"(c[mt][nt][3])
                        : "r"(a[mt][0]), "r"(a[mt][1]), "r"(a[mt][2]), "r"(a[mt][3]),
                          "r"(b[nt][0]), "r"(b[nt][1]));
        }
        __syncthreads();
    }

    // epilogue
#pragma unroll
    for (int mt = 0; mt < 2; mt++) {
        int r = row0 + warp_m * 32 + mt * 16 + gid;
#pragma unroll
        for (int nt = 0; nt < 4; nt++) {
            int cn = col0 + warp_n * 32 + nt * 8 + tig * 2;
            if (r < M)
                *(float2*)(C + (size_t)r * Nc + cn) = make_float2(c[mt][nt][0], c[mt][nt][1]);
            if (r + 8 < M)
                *(float2*)(C + (size_t)(r + 8) * Nc + cn) = make_float2(c[mt][nt][2], c[mt][nt][3]);
        }
    }
}

// ---------------- fused GATv2 edge softmax + aggregation ----------------
// One warp per (dst node, head). Online softmax over in-edges (CSR order).
__global__ void k_gat(const float* __restrict__ attn, const float* __restrict__ bias,
                      float* __restrict__ out) {
    int w = (blockIdx.x * blockDim.x + threadIdx.x) >> 5;
    int lane = threadIdx.x & 31;
    if (w >= NN * NH) return;
    int n = w / NH, h = w - n * NH;
    int base = h * DD + lane * 2;

    float2 fd2 = *(const float2*)(g_fd + (size_t)n * HD + base);
    float2 a2  = __ldg((const float2*)(attn + base));

    float m = -INFINITY, den = 0.f, accx = 0.f, accy = 0.f;
    int beg = g_off[n], end = g_off[n + 1];
    for (int i = beg; i < end; i++) {
        int s = g_esrc[i];
        float2 fs2 = *(const float2*)(g_fs + (size_t)s * HD + base);
        float vx = fs2.x + fd2.x; vx = vx > 0.f ? vx : 0.2f * vx;
        float vy = fs2.y + fd2.y; vy = vy > 0.f ? vy : 0.2f * vy;
        float p = fmaf(a2.x, vx, a2.y * vy);
#pragma unroll
        for (int o = 16; o; o >>= 1) p += __shfl_xor_sync(0xFFFFFFFFu, p, o);
        if (p <= m) {
            float ex = expf(p - m);
            den += ex;
            accx = fmaf(ex, fs2.x, accx);
            accy = fmaf(ex, fs2.y, accy);
        } else {
            float sc = expf(m - p);   // exp(-inf)=0 handles first edge
            den = fmaf(den, sc, 1.f);
            accx = fmaf(accx, sc, fs2.x);
            accy = fmaf(accy, sc, fs2.y);
            m = p;
        }
    }
    float inv = 1.f / fmaxf(den, 1e-9f);
    float2 b2 = __ldg((const float2*)(bias + base));
    float2 o2;
    o2.x = fmaf(accx, inv, b2.x);
    o2.y = fmaf(accy, inv, b2.y);
    *(float2*)(out + (size_t)n * HD + base) = o2;
}

// layer-3: mean over heads + graph pooling
__global__ void k_poolmean(const int* __restrict__ gid) {
    int idx = blockIdx.x * blockDim.x + threadIdx.x;
    if (idx >= NN * DD) return;
    int n = idx / DD, d = idx - n * DD;
    const float* p = g_acc + (size_t)n * HD;
    float v = (p[d] + p[DD + d] + p[2 * DD + d]) * (1.0f / 3.0f);
    int g = gid[n];
    atomicAdd(&g_gsum[g * DD + d], v);
    if (d == 0) atomicAdd(&g_gcnt[g], 1.0f);
}

// ---------------- pattern branch + classifier head ----------------
__global__ void k_head(const float* __restrict__ p1, const float* __restrict__ p2,
                       const float* __restrict__ p3,
                       const float* __restrict__ Wex, const float* __restrict__ bex,
                       const float* __restrict__ Wpat, const float* __restrict__ bpat,
                       const float* __restrict__ Wc1, const float* __restrict__ bc1,
                       const float* __restrict__ Wc2, const float* __restrict__ bc2,
                       const float* __restrict__ Wc3, const float* __restrict__ bc3,
                       float* __restrict__ out) {
    int g = blockIdx.x;
    int tid = threadIdx.x;
    __shared__ float s_ex[96];
    __shared__ float s_x[128];
    __shared__ float s_c1[64];
    __shared__ float s_c2[32];

    if (tid < 96) {
        int part = tid / 32, j = tid % 32;
        const float* p = (part == 0) ? p1 : (part == 1) ? p2 : p3;
        float acc = bex[j];
        for (int k = 0; k < PP; k++) acc = fmaf(p[g * PP + k], Wex[k * 32 + j], acc);
        s_ex[tid] = acc;
    }
    __syncthreads();

    if (tid < 64) {
        float cnt = fmaxf(g_gcnt[g], 1.0f);
        s_x[tid] = g_gsum[g * DD + tid] / cnt;
    } else {
        int j = tid - 64;
        float acc = bpat[j];
        for (int k = 0; k < 96; k++) acc = fmaf(s_ex[k], Wpat[k * PP + j], acc);
        s_x[tid] = acc > 0.f ? acc : 0.01f * acc;
    }
    __syncthreads();

    if (tid < 64) {
        float acc = bc1[tid];
        for (int k = 0; k < 128; k++) acc = fmaf(s_x[k], Wc1[k * 64 + tid], acc);
        s_c1[tid] = acc > 0.f ? acc : 0.01f * acc;
    }
    __syncthreads();

    if (tid < 32) {
        float acc = bc2[tid];
        for (int k = 0; k < 64; k++) acc = fmaf(s_c1[k], Wc2[k * 32 + tid], acc);
        s_c2[tid] = acc > 0.f ? acc : 0.01f * acc;
    }
    __syncthreads();

    if (tid < 2) {
        float acc = bc3[tid];
        for (int k = 0; k < 32; k++) acc = fmaf(s_c2[k], Wc3[k * 2 + tid], acc);
        out[g * 2 + tid] = acc;
    }
}

// ---------------- driver ----------------
static void run_layer(const float* x, int K,
                      const float* Ws, const float* Wd, const float* attn,
                      const float* bias, float* p_fs, float* p_fd, float* out) {
    dim3 grid(HD / TBN, cdiv(NN, TBM));
    k_gemm_tf32<<<grid, 256>>>(x, Ws, p_fs, NN, K, HD);
    k_gemm_tf32<<<grid, 256>>>(x, Wd, p_fd, NN, K, HD);
    k_gat<<<cdiv(NN * NH * 32, 256), 256>>>(attn, bias, out);
}

extern "C" void kernel_launch(void* const* d_in, const int* in_sizes, int n_in,
                              void* d_out, int out_size) {
    const float* inputs = (const float*)d_in[0];
    const int*   src    = (const int*)d_in[1];
    const int*   dst    = (const int*)d_in[2];
    const int*   gid    = (const int*)d_in[3];
    const float* p1     = (const float*)d_in[4];
    const float* p2     = (const float*)d_in[5];
    const float* p3     = (const float*)d_in[6];
    const float* W1s = (const float*)d_in[7],  *W1d = (const float*)d_in[8];
    const float* a1  = (const float*)d_in[9],  *b1  = (const float*)d_in[10];
    const float* W2s = (const float*)d_in[11], *W2d = (const float*)d_in[12];
    const float* a2  = (const float*)d_in[13], *b2  = (const float*)d_in[14];
    const float* W3s = (const float*)d_in[15], *W3d = (const float*)d_in[16];
    const float* a3  = (const float*)d_in[17], *b3  = (const float*)d_in[18];
    const float* Wex = (const float*)d_in[19], *bex = (const float*)d_in[20];
    const float* Wpat= (const float*)d_in[21], *bpat= (const float*)d_in[22];
    const float* Wc1 = (const float*)d_in[23], *bc1 = (const float*)d_in[24];
    const float* Wc2 = (const float*)d_in[25], *bc2 = (const float*)d_in[26];
    const float* Wc3 = (const float*)d_in[27], *bc3 = (const float*)d_in[28];

    float *p_fs, *p_fd, *p_h, *p_acc;
    cudaGetSymbolAddress((void**)&p_fs,  g_fs);
    cudaGetSymbolAddress((void**)&p_fd,  g_fd);
    cudaGetSymbolAddress((void**)&p_h,   g_h);
    cudaGetSymbolAddress((void**)&p_acc, g_acc);

    const int T = 256;
    // CSR build (dst is the same for all layers)
    k_init<<<cdiv(NN, T), T>>>();
    k_hist<<<cdiv(EE, T), T>>>(dst);
    k_scan<<<1, 1024>>>();
    k_scatter<<<cdiv(EE, T), T>>>(src, dst);

    run_layer(inputs, FIN, W1s, W1d, a1, b1, p_fs, p_fd, p_h);
    run_layer(p_h,    HD,  W2s, W2d, a2, b2, p_fs, p_fd, p_h);
    run_layer(p_h,    HD,  W3s, W3d, a3, b3, p_fs, p_fd, p_acc);

    k_poolmean<<<cdiv(NN * DD, T), T>>>(gid);
    k_head<<<GG, 128>>>(p1, p2, p3, Wex, bex, Wpat, bpat,
                        Wc1, bc1, Wc2, bc2, Wc3, bc3, (float*)d_out);
}